// round 3
// baseline (speedup 1.0000x reference)
#include <cuda_runtime.h>
#include <math.h>
#include <stdint.h>

#define NN   100000
#define EE   1600000
#define HID  128
#define HEADS 4
#define NEG  0.2f
#define LNEPS 1e-5f
#define GB   1563          // (NN+63)/64 gemm blocks
#define HB   6250          // (EE+255)/256 edge blocks
#define NB   391           // (NN+255)/256 node blocks
#define AGB  12500         // NN/8 warp-per-node blocks

// ---------------- device scratch ----------------
__device__ __align__(256) float g_h   [(size_t)NN*HID];
__device__ __align__(256) float g_agg [(size_t)NN*HID];
__device__ __align__(256) float g_xe8 [(size_t)NN*HID];
__device__ __align__(256) float g_gg  [(size_t)NN*HID];
__device__ __align__(256) float g_xgat[(size_t)NN*HID];
__device__ __align__(256) float g_z   [(size_t)NN*HID];
__device__ __align__(16)  float g_asrc[(size_t)NN*HEADS];
__device__ __align__(16)  float g_adst[(size_t)NN*HEADS];
__device__ float g_dinv[NN];
__device__ int   g_cnt_row[NN];
__device__ int   g_cnt_col[NN];
__device__ int   g_rptr[NN+1];
__device__ int   g_cptr[NN+1];
__device__ int   g_rcur[NN];
__device__ int   g_ccur[NN];
__device__ int   g_csr_rc[EE];
__device__ int   g_csr_cs[EE];
__device__ int   g_part[2*NB];
__device__ int   g_shift;

// ---------------- helpers ----------------
__device__ __forceinline__ float wsum(float x){
    #pragma unroll
    for (int o=16;o;o>>=1) x += __shfl_xor_sync(0xffffffffu, x, o);
    return x;
}
__device__ __forceinline__ float wmax(float x){
    #pragma unroll
    for (int o=16;o;o>>=1) x = fmaxf(x, __shfl_xor_sync(0xffffffffu, x, o));
    return x;
}
__device__ __forceinline__ int wsumi(int x){
    #pragma unroll
    for (int o=16;o;o>>=1) x += __shfl_xor_sync(0xffffffffu, x, o);
    return x;
}
__device__ __forceinline__ float lrelu(float x){ return x > 0.f ? x : NEG * x; }

typedef unsigned long long ull;
__device__ __forceinline__ ull pack2(float x, float y){
    ull r; asm("mov.b64 %0, {%1,%2};" : "=l"(r) : "f"(x), "f"(y)); return r;
}
__device__ __forceinline__ void unpack2(ull v, float &x, float &y){
    asm("mov.b64 {%0,%1}, %2;" : "=f"(x), "=f"(y) : "l"(v));
}
__device__ __forceinline__ void ffma2(ull &d, ull a, ull b){
    asm("fma.rn.f32x2 %0, %1, %2, %0;" : "+l"(d) : "l"(a), "l"(b));
}

// ================= role bodies =================

__device__ void detect_body(const int* ei){
    if (threadIdx.x == 0){
        int acc = 0;
        #pragma unroll 1
        for (int i = 1; i < 128; i += 2) acc |= ei[i];
        g_shift = (acc == 0) ? 1 : 0;
    }
}

__device__ void zero_body(int bid){
    int i = bid*256 + threadIdx.x;
    if (i < NN){ g_cnt_row[i]=0; g_cnt_col[i]=0; }
}

__device__ void hist_body(int bid, const int* ei){
    int e = bid*256 + threadIdx.x;
    if (e >= EE) return;
    int sh = g_shift;
    int r = ei[(size_t)e << sh];
    int c = ei[(size_t)(EE + e) << sh];
    atomicAdd(&g_cnt_row[r], 1);
    atomicAdd(&g_cnt_col[c], 1);
}

__device__ void fill_body(int bid, const int* ei){
    int e = bid*256 + threadIdx.x;
    if (e >= EE) return;
    int sh = g_shift;
    int r = ei[(size_t)e << sh];
    int c = ei[(size_t)(EE + e) << sh];
    int p = atomicAdd(&g_rcur[r], 1);
    g_csr_rc[p] = c;
    int q = atomicAdd(&g_ccur[c], 1);
    g_csr_cs[q] = r;
}

__device__ void dinv_body(int bid){
    int i = bid*256 + threadIdx.x;
    if (i < NN){
        int d = g_cnt_col[i];
        g_dinv[i] = d > 0 ? rsqrtf((float)d) : 0.f;
    }
}

// scan phase 1: per-256-chunk sums into g_part (t<NB: row, else col)
__device__ void scanp1_body(int bid){
    int t = bid;
    const int* cnt = (t < NB) ? g_cnt_row : g_cnt_col;
    int i = ((t < NB) ? t : t - NB)*256 + threadIdx.x;
    int v = (i < NN) ? cnt[i] : 0;
    int ws = wsumi(v);
    __shared__ int sums[8];
    int lane = threadIdx.x & 31, warp = threadIdx.x >> 5;
    if (lane == 0) sums[warp] = ws;
    __syncthreads();
    if (threadIdx.x == 0){
        int s = 0;
        #pragma unroll
        for (int w = 0; w < 8; w++) s += sums[w];
        g_part[t] = s;
    }
}

// scan phase 3: local exclusive scan + block offset -> ptr/cur
__device__ void scanp3_body(int bid){
    int t = bid;
    int isrow = (t < NB);
    const int* cnt = isrow ? g_cnt_row : g_cnt_col;
    int* ptr = isrow ? g_rptr : g_cptr;
    int* cur = isrow ? g_rcur : g_ccur;
    int i = (isrow ? t : t - NB)*256 + threadIdx.x;
    int v = (i < NN) ? cnt[i] : 0;
    int lane = threadIdx.x & 31, warp = threadIdx.x >> 5;
    int x = v;
    #pragma unroll
    for (int o=1;o<32;o<<=1){
        int y = __shfl_up_sync(0xffffffffu, x, o);
        if (lane >= o) x += y;
    }
    __shared__ int sums[8];
    __shared__ int offs[8];
    if (lane == 31) sums[warp] = x;
    __syncthreads();
    if (threadIdx.x == 0){
        int s = 0;
        #pragma unroll
        for (int w = 0; w < 8; w++){ offs[w] = s; s += sums[w]; }
    }
    __syncthreads();
    int ex = x - v + offs[warp] + g_part[t];
    if (i < NN){ ptr[i] = ex; cur[i] = ex; }
}

// ---------------- FFMA2 GEMM body: C[N,128] = A @ W^T (+bias)(+epi) ----
// 256 thr, 64 rows/block, K chunks of 64.  smem = 64*129 + 64*66 floats (~50KB)
// EPI: 0 plain, 1 residual+LN+ReLU, 2 plain + GAT attention logits
#define WPAD 129
#define APAD 66
#define SMEMF (64*WPAD + 64*APAD)
template<int KTOT, int EPI>
__device__ void gemm_body(int bid,
            const float* __restrict__ A0, const float* __restrict__ A1,
            const float* __restrict__ W,  const float* __restrict__ bias,
            const float* __restrict__ res, const float* __restrict__ gamma,
            const float* __restrict__ beta, float* __restrict__ C,
            const float* __restrict__ att_s, const float* __restrict__ att_d)
{
    extern __shared__ float smem[];
    float* Ws = smem;                 // [64][129]
    float* As = smem + 64*WPAD;       // [64][66]
    int tid  = threadIdx.x;
    int row0 = bid * 64;
    int lane = tid & 31, warp = tid >> 5;
    int r0 = warp * 8;

    ull acc[4][4];
    #pragma unroll
    for (int p = 0; p < 4; p++)
        #pragma unroll
        for (int j = 0; j < 4; j++){
            float b = bias ? bias[lane + 32*j] : 0.f;
            acc[p][j] = pack2(b, b);
        }

    const int NCH = KTOT / 64;
    #pragma unroll
    for (int ch = 0; ch < NCH; ch++){
        const float* A = (KTOT == 256 && ch >= 2) ? A1 : A0;
        int acol = (KTOT == 256) ? (ch & 1)*64 : ch*64;
        for (int idx = tid; idx < 128*64; idx += 256){
            int o = idx >> 6, k = idx & 63;
            Ws[k*WPAD + o] = W[(size_t)o*KTOT + ch*64 + k];
        }
        for (int idx = tid; idx < 64*64; idx += 256){
            int r = idx >> 6, k = idx & 63;
            int gr = row0 + r;
            As[k*APAD + r] = (gr < NN) ? A[(size_t)gr*128 + acol + k] : 0.f;
        }
        __syncthreads();

        #pragma unroll 2
        for (int k = 0; k < 64; k++){
            const float* wr = Ws + k*WPAD + lane;
            ull w0 = pack2(wr[0],  wr[0]);
            ull w1 = pack2(wr[32], wr[32]);
            ull w2 = pack2(wr[64], wr[64]);
            ull w3 = pack2(wr[96], wr[96]);
            const ull* ar = (const ull*)(As + k*APAD + r0);
            ull a0 = ar[0], a1 = ar[1], a2 = ar[2], a3 = ar[3];
            ffma2(acc[0][0], a0, w0); ffma2(acc[0][1], a0, w1);
            ffma2(acc[0][2], a0, w2); ffma2(acc[0][3], a0, w3);
            ffma2(acc[1][0], a1, w0); ffma2(acc[1][1], a1, w1);
            ffma2(acc[1][2], a1, w2); ffma2(acc[1][3], a1, w3);
            ffma2(acc[2][0], a2, w0); ffma2(acc[2][1], a2, w1);
            ffma2(acc[2][2], a2, w2); ffma2(acc[2][3], a2, w3);
            ffma2(acc[3][0], a3, w0); ffma2(acc[3][1], a3, w1);
            ffma2(acc[3][2], a3, w2); ffma2(acc[3][3], a3, w3);
        }
        __syncthreads();
    }

    float as_[4], ad_[4];
    if (EPI == 2){
        #pragma unroll
        for (int j = 0; j < 4; j++){ as_[j] = att_s[j*32+lane]; ad_[j] = att_d[j*32+lane]; }
    }

    #pragma unroll
    for (int p = 0; p < 4; p++){
        float v0[4], v1[4];
        #pragma unroll
        for (int j = 0; j < 4; j++) unpack2(acc[p][j], v0[j], v1[j]);
        #pragma unroll
        for (int half = 0; half < 2; half++){
            float* v = half ? v1 : v0;
            int gr = row0 + r0 + 2*p + half;
            if (gr >= NN) continue;
            if (EPI != 1){
                #pragma unroll
                for (int j = 0; j < 4; j++)
                    C[(size_t)gr*128 + lane + 32*j] = v[j];
                if (EPI == 2){
                    #pragma unroll
                    for (int j = 0; j < 4; j++){
                        float sj = wsum(v[j]*as_[j]);
                        float dj = wsum(v[j]*ad_[j]);
                        if (lane == 0){
                            g_asrc[(size_t)gr*4+j] = sj;
                            g_adst[(size_t)gr*4+j] = dj;
                        }
                    }
                }
            } else {
                #pragma unroll
                for (int j = 0; j < 4; j++)
                    v[j] += res[(size_t)gr*128 + lane + 32*j];
                float s = v[0]+v[1]+v[2]+v[3];
                float mu = wsum(s) * (1.f/128.f);
                float q = 0.f;
                #pragma unroll
                for (int j = 0; j < 4; j++){ float d = v[j]-mu; q = fmaf(d,d,q); }
                float sc = rsqrtf(wsum(q) * (1.f/128.f) + LNEPS);
                #pragma unroll
                for (int j = 0; j < 4; j++){
                    int c = lane + 32*j;
                    float o = (v[j]-mu)*sc*gamma[c] + beta[c];
                    C[(size_t)gr*128 + c] = fmaxf(o, 0.f);
                }
            }
        }
    }
}

// ---------------- E8 aggregation body ----------------
__device__ void e8agg_body(int bid){
    int w = bid*8 + (threadIdx.x >> 5);
    if (w >= NN) return;
    int lane = threadIdx.x & 31;
    int s = g_rptr[w], e = g_rptr[w+1];
    float4 acc = make_float4(0.f,0.f,0.f,0.f);
    #pragma unroll 2
    for (int i = s; i < e; i++){
        int c = g_csr_rc[i];
        float dv = g_dinv[c];
        float4 hv = ((const float4*)(g_h + (size_t)c*128))[lane];
        acc.x = fmaf(dv, hv.x, acc.x);
        acc.y = fmaf(dv, hv.y, acc.y);
        acc.z = fmaf(dv, hv.z, acc.z);
        acc.w = fmaf(dv, hv.w, acc.w);
    }
    float du = g_dinv[w];
    float4 o = make_float4(du*acc.x, du*acc.y, du*acc.z, du*acc.w);
    ((float4*)(g_agg + (size_t)w*128))[lane] = o;
}

// ---------------- GAT body ----------------
__device__ void gat_body(int bid, const float* __restrict__ bgat){
    int v = bid*8 + (threadIdx.x >> 5);
    if (v >= NN) return;
    int lane = threadIdx.x & 31;
    int s = g_cptr[v], e = g_cptr[v+1];

    float4 ad = ((const float4*)g_adst)[v];
    float4 asl = ((const float4*)g_asrc)[v];
    float es0 = lrelu(asl.x + ad.x), es1 = lrelu(asl.y + ad.y);
    float es2 = lrelu(asl.z + ad.z), es3 = lrelu(asl.w + ad.w);

    float m0 = es0, m1 = es1, m2 = es2, m3 = es3;
    for (int i = s + lane; i < e; i += 32){
        int u = g_csr_cs[i];
        float4 a = ((const float4*)g_asrc)[u];
        m0 = fmaxf(m0, lrelu(a.x + ad.x));
        m1 = fmaxf(m1, lrelu(a.y + ad.y));
        m2 = fmaxf(m2, lrelu(a.z + ad.z));
        m3 = fmaxf(m3, lrelu(a.w + ad.w));
    }
    m0 = wmax(m0); m1 = wmax(m1); m2 = wmax(m2); m3 = wmax(m3);

    float s0=0.f,s1=0.f,s2=0.f,s3=0.f;
    for (int i = s + lane; i < e; i += 32){
        int u = g_csr_cs[i];
        float4 a = ((const float4*)g_asrc)[u];
        s0 += __expf(lrelu(a.x + ad.x) - m0);
        s1 += __expf(lrelu(a.y + ad.y) - m1);
        s2 += __expf(lrelu(a.z + ad.z) - m2);
        s3 += __expf(lrelu(a.w + ad.w) - m3);
    }
    s0 = wsum(s0) + __expf(es0 - m0);
    s1 = wsum(s1) + __expf(es1 - m1);
    s2 = wsum(s2) + __expf(es2 - m2);
    s3 = wsum(s3) + __expf(es3 - m3);
    float i0 = 1.f/(s0+1e-16f), i1 = 1.f/(s1+1e-16f), i2 = 1.f/(s2+1e-16f), i3 = 1.f/(s3+1e-16f);

    int hidx = lane >> 3;
    float adh  = (hidx==0)?ad.x : (hidx==1)?ad.y : (hidx==2)?ad.z : ad.w;
    float mh   = (hidx==0)?m0  : (hidx==1)?m1  : (hidx==2)?m2  : m3;
    float ih   = (hidx==0)?i0  : (hidx==1)?i1  : (hidx==2)?i2  : i3;
    float esh  = (hidx==0)?es0 : (hidx==1)?es1 : (hidx==2)?es2 : es3;

    float4 acc = make_float4(0.f,0.f,0.f,0.f);
    #pragma unroll 2
    for (int i = s; i < e; i++){
        int u = g_csr_cs[i];
        float a = g_asrc[(size_t)u*4 + hidx];
        float alpha = __expf(lrelu(a + adh) - mh) * ih;
        float4 gv = ((const float4*)(g_gg + (size_t)u*128))[lane];
        acc.x = fmaf(alpha, gv.x, acc.x);
        acc.y = fmaf(alpha, gv.y, acc.y);
        acc.z = fmaf(alpha, gv.z, acc.z);
        acc.w = fmaf(alpha, gv.w, acc.w);
    }
    {
        float alpha = __expf(esh - mh) * ih;
        float4 gv = ((const float4*)(g_gg + (size_t)v*128))[lane];
        acc.x = fmaf(alpha, gv.x, acc.x);
        acc.y = fmaf(alpha, gv.y, acc.y);
        acc.z = fmaf(alpha, gv.z, acc.z);
        acc.w = fmaf(alpha, gv.w, acc.w);
    }
    float4 b = ((const float4*)bgat)[lane];
    acc.x += b.x; acc.y += b.y; acc.z += b.z; acc.w += b.w;
    ((float4*)(g_xgat + (size_t)v*128))[lane] = acc;
}

// ================= fused global kernels =================

__global__ void kInit(const int* ei){
    if (blockIdx.x == 0) detect_body(ei);
    else zero_body(blockIdx.x - 1);
}

__global__ __launch_bounds__(256)
void kEmbHist(const float* x, const float* W_emb, const float* b_emb, const int* ei){
    if (blockIdx.x < GB)
        gemm_body<128,0>(blockIdx.x, x, nullptr, W_emb, b_emb,
                         nullptr, nullptr, nullptr, g_h, nullptr, nullptr);
    else
        hist_body(blockIdx.x - GB, ei);
}

__global__ void kScanP1Dinv(){
    if (blockIdx.x < 2*NB) scanp1_body(blockIdx.x);
    else dinv_body(blockIdx.x - 2*NB);
}

__global__ __launch_bounds__(1024)
void kScanP2(){
    __shared__ int sh[1024];
    int tid = threadIdx.x;
    int half = tid >> 9, li = tid & 511;
    int idx = half ? NB + li : li;
    int v = (li < NB) ? g_part[idx] : 0;
    sh[tid] = v; __syncthreads();
    #pragma unroll
    for (int off = 1; off < 512; off <<= 1){
        int y = (li >= off) ? sh[tid - off] : 0;
        __syncthreads();
        sh[tid] += y;
        __syncthreads();
    }
    if (li < NB) g_part[idx] = sh[tid] - v;
    if (tid == 0){ g_rptr[NN] = EE; g_cptr[NN] = EE; }
}

__global__ void kScanP3(){ scanp3_body(blockIdx.x); }

__global__ __launch_bounds__(256)
void kGatGemmFill(const float* W_gat, const float* att_s, const float* att_d, const int* ei){
    if (blockIdx.x < GB)
        gemm_body<128,2>(blockIdx.x, g_h, nullptr, W_gat, nullptr,
                         nullptr, nullptr, nullptr, g_gg, att_s, att_d);
    else
        fill_body(blockIdx.x - GB, ei);
}

__global__ __launch_bounds__(256)
void kE8Agg(){ e8agg_body(blockIdx.x); }

__global__ __launch_bounds__(256)
void kGatE8Gemm(const float* bgat, const float* W_e8){
    if (blockIdx.x < AGB)
        gat_body(blockIdx.x, bgat);
    else
        gemm_body<128,0>(blockIdx.x - AGB, g_agg, nullptr, W_e8, nullptr,
                         nullptr, nullptr, nullptr, g_xe8, nullptr, nullptr);
}

__global__ __launch_bounds__(256)
void kFusGemm(const float* W_fus, const float* b_fus, const float* gamma, const float* beta){
    gemm_body<256,1>(blockIdx.x, g_xe8, g_xgat, W_fus, b_fus,
                     g_h, gamma, beta, g_z, nullptr, nullptr);
}

// ---------------- fused readout ----------------
__global__ __launch_bounds__(1024)
void k_readout(const float* __restrict__ Wr1, const float* __restrict__ br1,
               const float* __restrict__ Wr2, const float* __restrict__ br2,
               float* __restrict__ out)
{
    __shared__ ull Ws2[128*32];
    int tid = threadIdx.x;
    for (int idx = tid; idx < 128*32; idx += 1024){
        int k = idx >> 5, o = idx & 31;
        Ws2[idx] = pack2(Wr1[(size_t)o*128 + k], Wr1[(size_t)(o+32)*128 + k]);
    }
    __syncthreads();
    int warp = tid >> 5, lane = tid & 31;
    int node = blockIdx.x*32 + warp;
    if (node >= NN) return;

    float4 zv = ((const float4*)(g_z + (size_t)node*128))[lane];
    ull acc = pack2(br1[lane], br1[lane+32]);
    #pragma unroll 8
    for (int kb = 0; kb < 32; kb++){
        float zx = __shfl_sync(0xffffffffu, zv.x, kb);
        float zy = __shfl_sync(0xffffffffu, zv.y, kb);
        float zz = __shfl_sync(0xffffffffu, zv.z, kb);
        float zw = __shfl_sync(0xffffffffu, zv.w, kb);
        int k = kb*4;
        ffma2(acc, pack2(zx,zx), Ws2[(k+0)*32+lane]);
        ffma2(acc, pack2(zy,zy), Ws2[(k+1)*32+lane]);
        ffma2(acc, pack2(zz,zz), Ws2[(k+2)*32+lane]);
        ffma2(acc, pack2(zw,zw), Ws2[(k+3)*32+lane]);
    }
    float a0, a1; unpack2(acc, a0, a1);
    float r0 = fmaxf(a0, 0.f);
    float r1 = fmaxf(a1, 0.f);
    float p = fmaf(r0, Wr2[lane], r1 * Wr2[lane+32]);
    p = wsum(p);
    if (lane == 0){
        float xv = p + br2[0];
        out[node] = 1.f / (1.f + __expf(-xv));
    }
}

// ---------------- host ----------------
extern "C" void kernel_launch(void* const* d_in, const int* in_sizes, int n_in,
                              void* d_out, int out_size)
{
    const float* x       = (const float*)d_in[0];
    const int*   ei      = (const int*)  d_in[1];
    const float* W_emb   = (const float*)d_in[2];
    const float* b_emb   = (const float*)d_in[3];
    const float* W_e8    = (const float*)d_in[4];
    const float* W_gat   = (const float*)d_in[5];
    const float* att_src = (const float*)d_in[6];
    const float* att_dst = (const float*)d_in[7];
    const float* b_gat   = (const float*)d_in[8];
    const float* W_fus   = (const float*)d_in[9];
    const float* b_fus   = (const float*)d_in[10];
    const float* gamma   = (const float*)d_in[11];
    const float* beta    = (const float*)d_in[12];
    const float* W_r1    = (const float*)d_in[13];
    const float* b_r1    = (const float*)d_in[14];
    const float* W_r2    = (const float*)d_in[15];
    const float* b_r2    = (const float*)d_in[16];
    float* out = (float*)d_out;

    const int smB = SMEMF * 4;   // ~50KB
    cudaFuncSetAttribute(kEmbHist,    cudaFuncAttributeMaxDynamicSharedMemorySize, smB);
    cudaFuncSetAttribute(kGatGemmFill,cudaFuncAttributeMaxDynamicSharedMemorySize, smB);
    cudaFuncSetAttribute(kGatE8Gemm,  cudaFuncAttributeMaxDynamicSharedMemorySize, smB);
    cudaFuncSetAttribute(kFusGemm,    cudaFuncAttributeMaxDynamicSharedMemorySize, smB);

    kInit       <<<1 + NB, 256>>>(ei);
    kEmbHist    <<<GB + HB, 256, smB>>>(x, W_emb, b_emb, ei);
    kScanP1Dinv <<<2*NB + NB, 256>>>();
    kScanP2     <<<1, 1024>>>();
    kScanP3     <<<2*NB, 256>>>();
    kGatGemmFill<<<GB + HB, 256, smB>>>(W_gat, att_src, att_dst, ei);
    kE8Agg      <<<AGB, 256>>>();
    kGatE8Gemm  <<<AGB + GB, 256, smB>>>(b_gat, W_e8);
    kFusGemm    <<<GB, 256, smB>>>(W_fus, b_fus, gamma, beta);
    k_readout   <<<(NN+31)/32, 1024>>>(W_r1, b_r1, W_r2, b_r2, out);
}

// round 4
// speedup vs baseline: 1.4626x; 1.4626x over previous
#include <cuda_runtime.h>
#include <math.h>
#include <stdint.h>

#define NN   100000
#define EE   1600000
#define HID  128
#define HEADS 4
#define NEG  0.2f
#define LNEPS 1e-5f
#define NB   391           // (NN+255)/256

// ---------------- device scratch ----------------
__device__ __align__(256) float g_h   [(size_t)NN*HID];
__device__ __align__(256) float g_agg [(size_t)NN*HID];
__device__ __align__(256) float g_xe8 [(size_t)NN*HID];
__device__ __align__(256) float g_gg  [(size_t)NN*HID];
__device__ __align__(256) float g_xgat[(size_t)NN*HID];
__device__ __align__(256) float g_z   [(size_t)NN*HID];
__device__ __align__(16)  float g_asrc[(size_t)NN*HEADS];
__device__ __align__(16)  float g_adst[(size_t)NN*HEADS];
__device__ float g_dinv[NN];
__device__ int   g_cnt_row[NN];
__device__ int   g_cnt_col[NN];
__device__ int   g_rptr[NN+1];
__device__ int   g_cptr[NN+1];
__device__ int   g_rcur[NN];
__device__ int   g_ccur[NN];
__device__ int   g_csr_rc[EE];
__device__ int   g_csr_cs[EE];
__device__ int   g_part[2*NB];
__device__ int   g_shift;

// ---------------- helpers ----------------
__device__ __forceinline__ float wsum(float x){
    #pragma unroll
    for (int o=16;o;o>>=1) x += __shfl_xor_sync(0xffffffffu, x, o);
    return x;
}
__device__ __forceinline__ float wmax(float x){
    #pragma unroll
    for (int o=16;o;o>>=1) x = fmaxf(x, __shfl_xor_sync(0xffffffffu, x, o));
    return x;
}
__device__ __forceinline__ int wsumi(int x){
    #pragma unroll
    for (int o=16;o;o>>=1) x += __shfl_xor_sync(0xffffffffu, x, o);
    return x;
}
__device__ __forceinline__ float lrelu(float x){ return x > 0.f ? x : NEG * x; }

typedef unsigned long long ull;
__device__ __forceinline__ ull pack2(float x, float y){
    ull r; asm("mov.b64 %0, {%1,%2};" : "=l"(r) : "f"(x), "f"(y)); return r;
}
__device__ __forceinline__ void unpack2(ull v, float &x, float &y){
    asm("mov.b64 {%0,%1}, %2;" : "=f"(x), "=f"(y) : "l"(v));
}
__device__ __forceinline__ void ffma2(ull &d, ull a, ull b){
    asm("fma.rn.f32x2 %0, %1, %2, %0;" : "+l"(d) : "l"(a), "l"(b));
}

// ---------------- init: dtype detection + count zero ----------------
__global__ void kInit(const int* ei){
    if (blockIdx.x == 0){
        if (threadIdx.x == 0){
            int acc = 0;
            #pragma unroll 1
            for (int i = 1; i < 128; i += 2) acc |= ei[i];
            g_shift = (acc == 0) ? 1 : 0;
        }
    } else {
        int i = (blockIdx.x-1)*256 + threadIdx.x;
        if (i < NN){ g_cnt_row[i]=0; g_cnt_col[i]=0; }
    }
}

__global__ void k_hist(const int* ei){
    int e = blockIdx.x*blockDim.x + threadIdx.x;
    if (e >= EE) return;
    int sh = g_shift;
    int r = ei[(size_t)e << sh];
    int c = ei[(size_t)(EE + e) << sh];
    atomicAdd(&g_cnt_row[r], 1);
    atomicAdd(&g_cnt_col[c], 1);
}

// scan phase 1 (per-chunk sums) fused with dinv
__global__ void kScanP1Dinv(){
    int t = blockIdx.x;
    if (t < 2*NB){
        const int* cnt = (t < NB) ? g_cnt_row : g_cnt_col;
        int i = ((t < NB) ? t : t - NB)*256 + threadIdx.x;
        int v = (i < NN) ? cnt[i] : 0;
        int ws = wsumi(v);
        __shared__ int sums[8];
        int lane = threadIdx.x & 31, warp = threadIdx.x >> 5;
        if (lane == 0) sums[warp] = ws;
        __syncthreads();
        if (threadIdx.x == 0){
            int s = 0;
            #pragma unroll
            for (int w = 0; w < 8; w++) s += sums[w];
            g_part[t] = s;
        }
    } else {
        int i = (t - 2*NB)*256 + threadIdx.x;
        if (i < NN){
            int d = g_cnt_col[i];
            g_dinv[i] = d > 0 ? rsqrtf((float)d) : 0.f;
        }
    }
}

__global__ __launch_bounds__(1024)
void kScanP2(){
    __shared__ int sh[1024];
    int tid = threadIdx.x;
    int half = tid >> 9, li = tid & 511;
    int idx = half ? NB + li : li;
    int v = (li < NB) ? g_part[idx] : 0;
    sh[tid] = v; __syncthreads();
    #pragma unroll
    for (int off = 1; off < 512; off <<= 1){
        int y = (li >= off) ? sh[tid - off] : 0;
        __syncthreads();
        sh[tid] += y;
        __syncthreads();
    }
    if (li < NB) g_part[idx] = sh[tid] - v;
    if (tid == 0){ g_rptr[NN] = EE; g_cptr[NN] = EE; }
}

__global__ void kScanP3(){
    int t = blockIdx.x;
    int isrow = (t < NB);
    const int* cnt = isrow ? g_cnt_row : g_cnt_col;
    int* ptr = isrow ? g_rptr : g_cptr;
    int* cur = isrow ? g_rcur : g_ccur;
    int i = (isrow ? t : t - NB)*256 + threadIdx.x;
    int v = (i < NN) ? cnt[i] : 0;
    int lane = threadIdx.x & 31, warp = threadIdx.x >> 5;
    int x = v;
    #pragma unroll
    for (int o=1;o<32;o<<=1){
        int y = __shfl_up_sync(0xffffffffu, x, o);
        if (lane >= o) x += y;
    }
    __shared__ int sums[8];
    __shared__ int offs[8];
    if (lane == 31) sums[warp] = x;
    __syncthreads();
    if (threadIdx.x == 0){
        int s = 0;
        #pragma unroll
        for (int w = 0; w < 8; w++){ offs[w] = s; s += sums[w]; }
    }
    __syncthreads();
    int ex = x - v + offs[warp] + g_part[t];
    if (i < NN){ ptr[i] = ex; cur[i] = ex; }
}

__global__ void k_fill(const int* ei){
    int e = blockIdx.x*blockDim.x + threadIdx.x;
    if (e >= EE) return;
    int sh = g_shift;
    int r = ei[(size_t)e << sh];
    int c = ei[(size_t)(EE + e) << sh];
    int p = atomicAdd(&g_rcur[r], 1);
    g_csr_rc[p] = c;
    int q = atomicAdd(&g_ccur[c], 1);
    g_csr_cs[q] = r;
}

// ---------------- FFMA2 GEMM (R2 config: K chunks of 128, ~100KB smem) ----
// EPI: 0 plain, 1 residual+LN+ReLU, 2 plain + attention logits
#define WPAD 129
#define APAD 66
template<int KTOT, int EPI>
__global__ __launch_bounds__(256)
void k_gemm(const float* __restrict__ A0, const float* __restrict__ A1,
            const float* __restrict__ W,  const float* __restrict__ bias,
            const float* __restrict__ res, const float* __restrict__ gamma,
            const float* __restrict__ beta, float* __restrict__ C,
            const float* __restrict__ att_s, const float* __restrict__ att_d)
{
    extern __shared__ float smem[];
    float* Ws = smem;                 // [128][WPAD]
    float* As = smem + 128*WPAD;      // [128][APAD]
    int tid  = threadIdx.x;
    int row0 = blockIdx.x * 64;
    int lane = tid & 31, warp = tid >> 5;
    int r0 = warp * 8;

    ull acc[4][4];
    #pragma unroll
    for (int p = 0; p < 4; p++)
        #pragma unroll
        for (int j = 0; j < 4; j++){
            float b = bias ? bias[lane + 32*j] : 0.f;
            acc[p][j] = pack2(b, b);
        }

    const int NCH = KTOT / 128;
    #pragma unroll
    for (int ch = 0; ch < NCH; ch++){
        const float* A = (NCH == 2 && ch == 1) ? A1 : A0;
        for (int idx = tid; idx < 128*128; idx += 256){
            int o = idx >> 7, k = idx & 127;
            Ws[k*WPAD + o] = W[(size_t)o*KTOT + ch*128 + k];
        }
        for (int idx = tid; idx < 64*128; idx += 256){
            int r = idx >> 7, k = idx & 127;
            int gr = row0 + r;
            As[k*APAD + r] = (gr < NN) ? A[(size_t)gr*128 + k] : 0.f;
        }
        __syncthreads();

        #pragma unroll 2
        for (int k = 0; k < 128; k++){
            const float* wr = Ws + k*WPAD + lane;
            ull w0 = pack2(wr[0],  wr[0]);
            ull w1 = pack2(wr[32], wr[32]);
            ull w2 = pack2(wr[64], wr[64]);
            ull w3 = pack2(wr[96], wr[96]);
            const ull* ar = (const ull*)(As + k*APAD + r0);
            ull a0 = ar[0], a1 = ar[1], a2 = ar[2], a3 = ar[3];
            ffma2(acc[0][0], a0, w0); ffma2(acc[0][1], a0, w1);
            ffma2(acc[0][2], a0, w2); ffma2(acc[0][3], a0, w3);
            ffma2(acc[1][0], a1, w0); ffma2(acc[1][1], a1, w1);
            ffma2(acc[1][2], a1, w2); ffma2(acc[1][3], a1, w3);
            ffma2(acc[2][0], a2, w0); ffma2(acc[2][1], a2, w1);
            ffma2(acc[2][2], a2, w2); ffma2(acc[2][3], a2, w3);
            ffma2(acc[3][0], a3, w0); ffma2(acc[3][1], a3, w1);
            ffma2(acc[3][2], a3, w2); ffma2(acc[3][3], a3, w3);
        }
        __syncthreads();
    }

    float as_[4], ad_[4];
    if (EPI == 2){
        #pragma unroll
        for (int j = 0; j < 4; j++){ as_[j] = att_s[j*32+lane]; ad_[j] = att_d[j*32+lane]; }
    }

    #pragma unroll
    for (int p = 0; p < 4; p++){
        float v0[4], v1[4];
        #pragma unroll
        for (int j = 0; j < 4; j++) unpack2(acc[p][j], v0[j], v1[j]);
        #pragma unroll
        for (int half = 0; half < 2; half++){
            float* v = half ? v1 : v0;
            int gr = row0 + r0 + 2*p + half;
            if (gr >= NN) continue;
            if (EPI != 1){
                #pragma unroll
                for (int j = 0; j < 4; j++)
                    C[(size_t)gr*128 + lane + 32*j] = v[j];
                if (EPI == 2){
                    #pragma unroll
                    for (int j = 0; j < 4; j++){
                        float sj = wsum(v[j]*as_[j]);
                        float dj = wsum(v[j]*ad_[j]);
                        if (lane == 0){
                            g_asrc[(size_t)gr*4+j] = sj;
                            g_adst[(size_t)gr*4+j] = dj;
                        }
                    }
                }
            } else {
                #pragma unroll
                for (int j = 0; j < 4; j++)
                    v[j] += res[(size_t)gr*128 + lane + 32*j];
                float s = v[0]+v[1]+v[2]+v[3];
                float mu = wsum(s) * (1.f/128.f);
                float q = 0.f;
                #pragma unroll
                for (int j = 0; j < 4; j++){ float d = v[j]-mu; q = fmaf(d,d,q); }
                float sc = rsqrtf(wsum(q) * (1.f/128.f) + LNEPS);
                #pragma unroll
                for (int j = 0; j < 4; j++){
                    int c = lane + 32*j;
                    float o = (v[j]-mu)*sc*gamma[c] + beta[c];
                    C[(size_t)gr*128 + c] = fmaxf(o, 0.f);
                }
            }
        }
    }
}

// ---------------- E8 aggregation ----------------
__global__ void k_e8agg(){
    int w = (blockIdx.x*blockDim.x + threadIdx.x) >> 5;
    if (w >= NN) return;
    int lane = threadIdx.x & 31;
    int s = g_rptr[w], e = g_rptr[w+1];
    float4 acc = make_float4(0.f,0.f,0.f,0.f);
    #pragma unroll 2
    for (int i = s; i < e; i++){
        int c = g_csr_rc[i];
        float dv = g_dinv[c];
        float4 hv = ((const float4*)(g_h + (size_t)c*128))[lane];
        acc.x = fmaf(dv, hv.x, acc.x);
        acc.y = fmaf(dv, hv.y, acc.y);
        acc.z = fmaf(dv, hv.z, acc.z);
        acc.w = fmaf(dv, hv.w, acc.w);
    }
    float du = g_dinv[w];
    float4 o = make_float4(du*acc.x, du*acc.y, du*acc.z, du*acc.w);
    ((float4*)(g_agg + (size_t)w*128))[lane] = o;
}

// ---------------- GAT ----------------
__global__ void k_gat(const float* __restrict__ bgat){
    int v = (blockIdx.x*blockDim.x + threadIdx.x) >> 5;
    if (v >= NN) return;
    int lane = threadIdx.x & 31;
    int s = g_cptr[v], e = g_cptr[v+1];

    float4 ad = ((const float4*)g_adst)[v];
    float4 asl = ((const float4*)g_asrc)[v];
    float es0 = lrelu(asl.x + ad.x), es1 = lrelu(asl.y + ad.y);
    float es2 = lrelu(asl.z + ad.z), es3 = lrelu(asl.w + ad.w);

    float m0 = es0, m1 = es1, m2 = es2, m3 = es3;
    for (int i = s + lane; i < e; i += 32){
        int u = g_csr_cs[i];
        float4 a = ((const float4*)g_asrc)[u];
        m0 = fmaxf(m0, lrelu(a.x + ad.x));
        m1 = fmaxf(m1, lrelu(a.y + ad.y));
        m2 = fmaxf(m2, lrelu(a.z + ad.z));
        m3 = fmaxf(m3, lrelu(a.w + ad.w));
    }
    m0 = wmax(m0); m1 = wmax(m1); m2 = wmax(m2); m3 = wmax(m3);

    float s0=0.f,s1=0.f,s2=0.f,s3=0.f;
    for (int i = s + lane; i < e; i += 32){
        int u = g_csr_cs[i];
        float4 a = ((const float4*)g_asrc)[u];
        s0 += __expf(lrelu(a.x + ad.x) - m0);
        s1 += __expf(lrelu(a.y + ad.y) - m1);
        s2 += __expf(lrelu(a.z + ad.z) - m2);
        s3 += __expf(lrelu(a.w + ad.w) - m3);
    }
    s0 = wsum(s0) + __expf(es0 - m0);
    s1 = wsum(s1) + __expf(es1 - m1);
    s2 = wsum(s2) + __expf(es2 - m2);
    s3 = wsum(s3) + __expf(es3 - m3);
    float i0 = 1.f/(s0+1e-16f), i1 = 1.f/(s1+1e-16f), i2 = 1.f/(s2+1e-16f), i3 = 1.f/(s3+1e-16f);

    int hidx = lane >> 3;
    float adh  = (hidx==0)?ad.x : (hidx==1)?ad.y : (hidx==2)?ad.z : ad.w;
    float mh   = (hidx==0)?m0  : (hidx==1)?m1  : (hidx==2)?m2  : m3;
    float ih   = (hidx==0)?i0  : (hidx==1)?i1  : (hidx==2)?i2  : i3;
    float esh  = (hidx==0)?es0 : (hidx==1)?es1 : (hidx==2)?es2 : es3;

    float4 acc = make_float4(0.f,0.f,0.f,0.f);
    #pragma unroll 2
    for (int i = s; i < e; i++){
        int u = g_csr_cs[i];
        float a = g_asrc[(size_t)u*4 + hidx];
        float alpha = __expf(lrelu(a + adh) - mh) * ih;
        float4 gv = ((const float4*)(g_gg + (size_t)u*128))[lane];
        acc.x = fmaf(alpha, gv.x, acc.x);
        acc.y = fmaf(alpha, gv.y, acc.y);
        acc.z = fmaf(alpha, gv.z, acc.z);
        acc.w = fmaf(alpha, gv.w, acc.w);
    }
    {
        float alpha = __expf(esh - mh) * ih;
        float4 gv = ((const float4*)(g_gg + (size_t)v*128))[lane];
        acc.x = fmaf(alpha, gv.x, acc.x);
        acc.y = fmaf(alpha, gv.y, acc.y);
        acc.z = fmaf(alpha, gv.z, acc.z);
        acc.w = fmaf(alpha, gv.w, acc.w);
    }
    float4 b = ((const float4*)bgat)[lane];
    acc.x += b.x; acc.y += b.y; acc.z += b.z; acc.w += b.w;
    ((float4*)(g_xgat + (size_t)v*128))[lane] = acc;
}

// ---------------- fused readout ----------------
__global__ __launch_bounds__(1024)
void k_readout(const float* __restrict__ Wr1, const float* __restrict__ br1,
               const float* __restrict__ Wr2, const float* __restrict__ br2,
               float* __restrict__ out)
{
    __shared__ ull Ws2[128*32];
    int tid = threadIdx.x;
    for (int idx = tid; idx < 128*32; idx += 1024){
        int k = idx >> 5, o = idx & 31;
        Ws2[idx] = pack2(Wr1[(size_t)o*128 + k], Wr1[(size_t)(o+32)*128 + k]);
    }
    __syncthreads();
    int warp = tid >> 5, lane = tid & 31;
    int node = blockIdx.x*32 + warp;
    if (node >= NN) return;

    float4 zv = ((const float4*)(g_z + (size_t)node*128))[lane];
    ull acc = pack2(br1[lane], br1[lane+32]);
    #pragma unroll 8
    for (int kb = 0; kb < 32; kb++){
        float zx = __shfl_sync(0xffffffffu, zv.x, kb);
        float zy = __shfl_sync(0xffffffffu, zv.y, kb);
        float zz = __shfl_sync(0xffffffffu, zv.z, kb);
        float zw = __shfl_sync(0xffffffffu, zv.w, kb);
        int k = kb*4;
        ffma2(acc, pack2(zx,zx), Ws2[(k+0)*32+lane]);
        ffma2(acc, pack2(zy,zy), Ws2[(k+1)*32+lane]);
        ffma2(acc, pack2(zz,zz), Ws2[(k+2)*32+lane]);
        ffma2(acc, pack2(zw,zw), Ws2[(k+3)*32+lane]);
    }
    float a0, a1; unpack2(acc, a0, a1);
    float r0 = fmaxf(a0, 0.f);
    float r1 = fmaxf(a1, 0.f);
    float p = fmaf(r0, Wr2[lane], r1 * Wr2[lane+32]);
    p = wsum(p);
    if (lane == 0){
        float xv = p + br2[0];
        out[node] = 1.f / (1.f + __expf(-xv));
    }
}

// ---------------- host ----------------
extern "C" void kernel_launch(void* const* d_in, const int* in_sizes, int n_in,
                              void* d_out, int out_size)
{
    const float* x       = (const float*)d_in[0];
    const int*   ei      = (const int*)  d_in[1];
    const float* W_emb   = (const float*)d_in[2];
    const float* b_emb   = (const float*)d_in[3];
    const float* W_e8    = (const float*)d_in[4];
    const float* W_gat   = (const float*)d_in[5];
    const float* att_src = (const float*)d_in[6];
    const float* att_dst = (const float*)d_in[7];
    const float* b_gat   = (const float*)d_in[8];
    const float* W_fus   = (const float*)d_in[9];
    const float* b_fus   = (const float*)d_in[10];
    const float* gamma   = (const float*)d_in[11];
    const float* beta    = (const float*)d_in[12];
    const float* W_r1    = (const float*)d_in[13];
    const float* b_r1    = (const float*)d_in[14];
    const float* W_r2    = (const float*)d_in[15];
    const float* b_r2    = (const float*)d_in[16];
    float* out = (float*)d_out;

    float *h, *agg, *xe8, *gg, *xgat, *z;
    cudaGetSymbolAddress((void**)&h,    g_h);
    cudaGetSymbolAddress((void**)&agg,  g_agg);
    cudaGetSymbolAddress((void**)&xe8,  g_xe8);
    cudaGetSymbolAddress((void**)&gg,   g_gg);
    cudaGetSymbolAddress((void**)&xgat, g_xgat);
    cudaGetSymbolAddress((void**)&z,    g_z);

    const int smB = (128*WPAD + 128*APAD) * 4;   // ~100KB
    cudaFuncSetAttribute(k_gemm<128,0>, cudaFuncAttributeMaxDynamicSharedMemorySize, smB);
    cudaFuncSetAttribute(k_gemm<128,2>, cudaFuncAttributeMaxDynamicSharedMemorySize, smB);
    cudaFuncSetAttribute(k_gemm<256,1>, cudaFuncAttributeMaxDynamicSharedMemorySize, smB);

    const int gB = (NN + 63) / 64;

    kInit       <<<1 + NB, 256>>>(ei);                        // 0
    k_hist      <<<(EE+255)/256, 256>>>(ei);                  // 1
    kScanP1Dinv <<<2*NB + NB, 256>>>();                       // 2
    kScanP2     <<<1, 1024>>>();                              // 3
    kScanP3     <<<2*NB, 256>>>();                            // 4
    k_gemm<128,0><<<gB, 256, smB>>>(x, nullptr, W_emb, b_emb, // 5 (profiled)
            nullptr, nullptr, nullptr, h, nullptr, nullptr);
    k_fill      <<<(EE+255)/256, 256>>>(ei);                  // 6
    k_gemm<128,2><<<gB, 256, smB>>>(h, nullptr, W_gat, nullptr,
            nullptr, nullptr, nullptr, gg, att_src, att_dst); // 7
    k_e8agg     <<<(NN*32+255)/256, 256>>>();                 // 8
    k_gemm<128,0><<<gB, 256, smB>>>(agg, nullptr, W_e8, nullptr,
            nullptr, nullptr, nullptr, xe8, nullptr, nullptr);// 9
    k_gat       <<<(NN*32+255)/256, 256>>>(b_gat);            // 10
    k_gemm<256,1><<<gB, 256, smB>>>(xe8, xgat, W_fus, b_fus,
            h, gamma, beta, z, nullptr, nullptr);             // 11
    k_readout   <<<(NN+31)/32, 1024>>>(W_r1, b_r1, W_r2, b_r2, out);
}